// round 8
// baseline (speedup 1.0000x reference)
#include <cuda_runtime.h>
#include <cuda_bf16.h>

// SemiLoss focal loss (gamma=6), single fused kernel, max-occupancy flat map.
//   logits : [N, K, P] f32
//   seg    : [N, P]    int64 or int32 (runtime-sniffed)
//   label  : [N]       same int dtype
//   loss = -sum_{n: label[n]!=0} sum_p (1-exp(lp))^6 * lp / count(label!=0)
//   out  = [loss, 0, loss, 0, ...]
//
// Key insight: total active work is only cnt*P (~0.9M) pixels. At full
// occupancy (303k threads) each thread owns ~3 pixels, so the kernel is one
// latency window: issue ALL seg loads (independent), then ALL gathers
// (independent), then math. Exposed latency ~= 2 load round trips total.
// Grid = 8 blocks/SM, __launch_bounds__(256,8) keeps regs <= 32 so all
// 2048 threads/SM are resident.
//
// Completion: atomicAdd(g_total) + threadfence + atomicInc(g_done) wrapping
// at gridDim.x (self-resetting); last block finalizes out and resets g_total
// so the kernel is deterministic across CUDA-graph replays.

#define MAXROWS 256
#define THREADS 256
#define BLK_PER_SM 8

__device__ double       g_total = 0.0;
__device__ unsigned int g_done  = 0u;

__device__ __forceinline__ float focal_term(float lp)
{
    float pt = expf(lp);
    float u  = 1.0f - pt;
    float u2 = u * u;
    return u2 * u2 * u2 * lp;   // positive form; negated at the end
}

__global__ __launch_bounds__(THREADS, BLK_PER_SM)
void semiloss_fused(const float* __restrict__ logits,
                    const void*  __restrict__ seg,
                    const void*  __restrict__ label,
                    int N, int K, int P,
                    float* __restrict__ out, int out_size)
{
    const int tid = threadIdx.x;

    // ---- dtype sniff: int64 (LE) => every odd 32-bit word of seg is 0 ----
    __shared__ int s_is64;
    if (tid < 32) {
        const int* w = (const int*)seg;
        unsigned b = __ballot_sync(0xffffffffu, w[2 * tid + 1] == 0);
        if (tid == 0) s_is64 = (b == 0xffffffffu) ? 1 : 0;
    }
    __syncthreads();
    const int is64 = s_is64;

    // ---- build active-row map with ballots ----
    __shared__ unsigned s_masks[MAXROWS / 32];
    __shared__ short    s_rowOf[MAXROWS];   // ordinal -> row
    const int nwords = (N + 31) >> 5;
    {
        bool a = false;
        if (tid < N) {
            long long lv;
            if (is64) lv = ((const long long*)label)[tid];
            else      lv = (long long)((const int*)label)[tid];
            a = (lv != 0);
        }
        unsigned b = __ballot_sync(0xffffffffu, a);
        if ((tid & 31) == 0 && (tid >> 5) < nwords)
            s_masks[tid >> 5] = b;
    }
    __syncthreads();

    int cnt = 0;
    for (int j = 0; j < nwords; ++j) cnt += __popc(s_masks[j]);

    if (tid < N) {
        int w = tid >> 5, l = tid & 31;
        if ((s_masks[w] >> l) & 1u) {
            int pre = 0;
            for (int j = 0; j < w; ++j) pre += __popc(s_masks[j]);
            pre += __popc(s_masks[w] & ((1u << l) - 1u));
            s_rowOf[pre] = (short)tid;
        }
    }
    __syncthreads();

    // ---- flat gather-reduce: one predicated batch-4 latency window ----
    const int tot = cnt * P;
    const int S   = gridDim.x * blockDim.x;
    float acc = 0.0f;
    const size_t KP = (size_t)K * (size_t)P;

    for (int g0 = blockIdx.x * blockDim.x + tid; g0 < tot; g0 += 4 * S) {
        // addresses (predicated)
        int  row[4], p[4];
        bool v[4];
        #pragma unroll
        for (int i = 0; i < 4; ++i) {
            int f = g0 + i * S;
            v[i] = (f < tot);
            int q = v[i] ? (f / P) : 0;
            p[i]   = f - q * P;
            row[i] = s_rowOf[q];
        }
        // all seg loads (independent)
        int c[4] = {0, 0, 0, 0};
        if (is64) {
            const long long* sp = (const long long*)seg;
            #pragma unroll
            for (int i = 0; i < 4; ++i)
                if (v[i]) c[i] = (int)__ldg(sp + (size_t)row[i] * P + p[i]);
        } else {
            const int* sp = (const int*)seg;
            #pragma unroll
            for (int i = 0; i < 4; ++i)
                if (v[i]) c[i] = __ldg(sp + (size_t)row[i] * P + p[i]);
        }
        // all gathers (independent)
        float l[4];
        #pragma unroll
        for (int i = 0; i < 4; ++i)
            l[i] = v[i] ? __ldg(logits + (size_t)row[i] * KP
                                       + (size_t)c[i] * P + p[i]) : 0.0f;
        // math (focal_term(0) == 0, so invalid lanes contribute nothing)
        #pragma unroll
        for (int i = 0; i < 4; ++i)
            acc += focal_term(l[i]);
    }

    // ---- block reduction (float -> double at the end) ----
    for (int off = 16; off > 0; off >>= 1)
        acc += __shfl_down_sync(0xffffffffu, acc, off);
    __shared__ double s_part[8];
    const int lane = tid & 31, wid = tid >> 5;
    if (lane == 0) s_part[wid] = (double)acc;
    __syncthreads();

    __shared__ int s_islast;
    if (tid == 0) {
        double vsum = 0.0;
        #pragma unroll
        for (int w = 0; w < 8; ++w) vsum += s_part[w];
        if (vsum != 0.0) atomicAdd(&g_total, vsum);
        __threadfence();
        unsigned old = atomicInc(&g_done, gridDim.x - 1u);
        s_islast = (old == gridDim.x - 1u) ? 1 : 0;
    }
    __syncthreads();

    // ---- last block: finalize ----
    if (s_islast) {
        __shared__ float s_loss;
        if (tid == 0) {
            double tot_d = *((volatile double*)&g_total);
            double cd    = (cnt > 0) ? (double)cnt : 1.0;
            s_loss = (float)(-tot_d / cd);
            g_total = 0.0;          // reset for next graph replay
            __threadfence();
        }
        __syncthreads();
        float loss = s_loss;
        for (int i = tid; i < out_size; i += blockDim.x)
            out[i] = (i == 0 || i == 2) ? loss : 0.0f;
    }
}

extern "C" void kernel_launch(void* const* d_in, const int* in_sizes, int n_in,
                              void* d_out, int out_size)
{
    const float* logits = (const float*)d_in[0];
    const void*  seg    = d_in[1];
    const void*  label  = d_in[2];

    int N = in_sizes[2];                 // B*S
    int P = in_sizes[1] / N;             // H*W
    int K = in_sizes[0] / in_sizes[1];   // classes

    // 8 blocks/SM on 148-SM B200 -> 2048 threads/SM resident
    const int BLOCKS = 148 * BLK_PER_SM;

    semiloss_fused<<<BLOCKS, THREADS>>>(logits, seg, label,
                                        N, K, P,
                                        (float*)d_out, out_size);
}

// round 9
// speedup vs baseline: 1.1959x; 1.1959x over previous
#include <cuda_runtime.h>
#include <cuda_bf16.h>

// SemiLoss focal loss (gamma=6), single fused kernel.
// R3 structure (proven fastest) with finer work granularity:
//   - 128-thread blocks, 1024-pixel units, 8 px/thread (MLP=8 per thread)
//   - unit -> (active-row ordinal, sub-chunk) mapping; only the first
//     cnt*unitsPerRow block indices do gather work, so the RR block->SM
//     scheduler spreads ~5.8 working blocks per SM (vs 2.9 in R3).
//   - no per-pixel division: row resolved once per block.
//
//   logits : [N, K, P] f32
//   seg    : [N, P]    int64 or int32 (runtime-sniffed)
//   label  : [N]       same int dtype
//   loss = -sum_{n: label[n]!=0} sum_p (1-exp(lp))^6 * lp / count(label!=0)
//   out  = [loss, 0, loss, 0, ...]
//
// Completion: atomicAdd(g_total) + threadfence + atomicInc(g_done) wrapping
// at gridDim.x (self-resetting); last block finalizes out and resets g_total
// so the kernel is deterministic across CUDA-graph replays.

#define THREADS   128
#define PXPT      8                  // pixels per thread
#define UNIT_PX   (THREADS * PXPT)   // 1024
#define MAXROWS   128                // N <= 128 (ballot mapper, 1 pass)

__device__ double       g_total = 0.0;
__device__ unsigned int g_done  = 0u;

__device__ __forceinline__ float focal_term(float lp)
{
    float pt = expf(lp);
    float u  = 1.0f - pt;
    float u2 = u * u;
    return u2 * u2 * u2 * lp;   // positive form; negated at the end
}

__global__ __launch_bounds__(THREADS)
void semiloss_fused(const float* __restrict__ logits,
                    const void*  __restrict__ seg,
                    const void*  __restrict__ label,
                    int N, int K, int P, int unitsPerRow,
                    float* __restrict__ out, int out_size)
{
    const int tid = threadIdx.x;

    // ---- dtype sniff: int64 (LE) => every odd 32-bit word of seg is 0 ----
    __shared__ int s_is64;
    if (tid < 32) {
        const int* w = (const int*)seg;
        unsigned b = __ballot_sync(0xffffffffu, w[2 * tid + 1] == 0);
        if (tid == 0) s_is64 = (b == 0xffffffffu) ? 1 : 0;
    }
    __syncthreads();
    const int is64 = s_is64;

    // ---- build active-row map with ballots ----
    __shared__ unsigned s_masks[MAXROWS / 32];
    __shared__ short    s_rowOf[MAXROWS];   // ordinal -> row
    const int nwords = (N + 31) >> 5;
    {
        bool a = false;
        if (tid < N) {
            long long lv;
            if (is64) lv = ((const long long*)label)[tid];
            else      lv = (long long)((const int*)label)[tid];
            a = (lv != 0);
        }
        unsigned b = __ballot_sync(0xffffffffu, a);
        if ((tid & 31) == 0 && (tid >> 5) < nwords)
            s_masks[tid >> 5] = b;
    }
    __syncthreads();

    int cnt = 0;
    for (int j = 0; j < nwords; ++j) cnt += __popc(s_masks[j]);

    if (tid < N) {
        int w = tid >> 5, l = tid & 31;
        if ((s_masks[w] >> l) & 1u) {
            int pre = 0;
            for (int j = 0; j < w; ++j) pre += __popc(s_masks[j]);
            pre += __popc(s_masks[w] & ((1u << l) - 1u));
            s_rowOf[pre] = (short)tid;
        }
    }
    __syncthreads();

    // ---- gather-reduce over this block's unit (if any) ----
    float acc = 0.0f;
    {
        const int u = blockIdx.x;
        const int q = u / unitsPerRow;             // active-row ordinal
        if (q < cnt) {
            const int sub = u - q * unitsPerRow;
            const int row = s_rowOf[q];
            const int p0  = sub * UNIT_PX + tid;
            const float* base = logits + (size_t)row * (size_t)K * (size_t)P;

            if (p0 + (PXPT - 1) * THREADS < P) {
                int c[PXPT];
                if (is64) {
                    const long long* s = (const long long*)seg + (size_t)row * P;
                    #pragma unroll
                    for (int i = 0; i < PXPT; ++i)
                        c[i] = (int)__ldg(s + p0 + THREADS * i);
                } else {
                    const int* s = (const int*)seg + (size_t)row * P;
                    #pragma unroll
                    for (int i = 0; i < PXPT; ++i)
                        c[i] = __ldg(s + p0 + THREADS * i);
                }
                float l[PXPT];
                #pragma unroll
                for (int i = 0; i < PXPT; ++i)
                    l[i] = __ldg(base + (size_t)c[i] * P + p0 + THREADS * i);
                #pragma unroll
                for (int i = 0; i < PXPT; ++i)
                    acc += focal_term(l[i]);
            } else {
                #pragma unroll
                for (int i = 0; i < PXPT; ++i) {
                    int p = p0 + THREADS * i;
                    if (p >= P) break;
                    int cc;
                    if (is64) cc = (int)((const long long*)seg)[(size_t)row * P + p];
                    else      cc = ((const int*)seg)[(size_t)row * P + p];
                    acc += focal_term(__ldg(base + (size_t)cc * P + p));
                }
            }
        }
    }

    // ---- block reduction (4 warps) ----
    for (int off = 16; off > 0; off >>= 1)
        acc += __shfl_down_sync(0xffffffffu, acc, off);
    __shared__ double s_part[4];
    const int lane = tid & 31, wid = tid >> 5;
    if (lane == 0) s_part[wid] = (double)acc;
    __syncthreads();

    __shared__ int s_islast;
    if (tid == 0) {
        double v = s_part[0] + s_part[1] + s_part[2] + s_part[3];
        if (v != 0.0) atomicAdd(&g_total, v);
        __threadfence();
        unsigned old = atomicInc(&g_done, gridDim.x - 1u);
        s_islast = (old == gridDim.x - 1u) ? 1 : 0;
    }
    __syncthreads();

    // ---- last block: finalize ----
    if (s_islast) {
        __shared__ float s_loss;
        if (tid == 0) {
            double tot = *((volatile double*)&g_total);
            double cd  = (cnt > 0) ? (double)cnt : 1.0;
            s_loss = (float)(-tot / cd);
            g_total = 0.0;          // reset for next graph replay
            __threadfence();
        }
        __syncthreads();
        float loss = s_loss;
        for (int i = tid; i < out_size; i += blockDim.x)
            out[i] = (i == 0 || i == 2) ? loss : 0.0f;
    }
}

extern "C" void kernel_launch(void* const* d_in, const int* in_sizes, int n_in,
                              void* d_out, int out_size)
{
    const float* logits = (const float*)d_in[0];
    const void*  seg    = d_in[1];
    const void*  label  = d_in[2];

    int N = in_sizes[2];                 // B*S
    int P = in_sizes[1] / N;             // H*W
    int K = in_sizes[0] / in_sizes[1];   // classes

    int unitsPerRow = (P + UNIT_PX - 1) / UNIT_PX;
    unsigned int blocks = (unsigned int)N * (unsigned int)unitsPerRow;

    semiloss_fused<<<blocks, THREADS>>>(logits, seg, label,
                                        N, K, P, unitsPerRow,
                                        (float*)d_out, out_size);
}